// round 1
// baseline (speedup 1.0000x reference)
#include <cuda_runtime.h>
#include <cuda_bf16.h>

#define B_    16
#define CIN_  256
#define COUT_ 256
#define H_    64
#define W_    64
#define SDIM_ 512

// mod_scale = 1/sqrt(CIN*K*K) = 1/48 ; scale^2 = 1/2304
#define MOD_SCALE (1.0f / 48.0f)
#define SCALE2    (1.0f / 2304.0f)

// small scratch (allowed: __device__ globals)
__device__ float g_s[B_ * CIN_];        // style projection s[b][ci]
__device__ float g_demod[B_ * COUT_];   // demod[b][co]
__device__ float g_wsq[COUT_ * CIN_];   // sum_k weight^2

// ---------------------------------------------------------------------------
// Kernel 1: style projection  s[b][ci] = style[b] @ style_w[:,ci] + style_b[ci]
// grid = B_, block = CIN_
__global__ void k_style_proj(const float* __restrict__ style,
                             const float* __restrict__ style_w,
                             const float* __restrict__ style_b) {
    __shared__ float st[SDIM_];
    const int b = blockIdx.x;
    const int ci = threadIdx.x;
    for (int k = threadIdx.x; k < SDIM_; k += blockDim.x)
        st[k] = style[b * SDIM_ + k];
    __syncthreads();
    float acc = style_b[ci];
    #pragma unroll 8
    for (int k = 0; k < SDIM_; k++)
        acc += st[k] * style_w[k * CIN_ + ci];
    g_s[b * CIN_ + ci] = acc;
}

// ---------------------------------------------------------------------------
// Kernel 2: wsq[co][ci] = sum_k weight[co,ci,k]^2
// grid = COUT_, block = CIN_
__global__ void k_wsq(const float* __restrict__ weight) {
    const int idx = blockIdx.x * blockDim.x + threadIdx.x;  // co*CIN + ci
    const float* wp = weight + idx * 9;
    float s = 0.f;
    #pragma unroll
    for (int k = 0; k < 9; k++) { float v = wp[k]; s += v * v; }
    g_wsq[idx] = s;
}

// ---------------------------------------------------------------------------
// Kernel 3: demod[b][co] = rsqrt(scale2 * sum_ci s[b,ci]^2 * wsq[co,ci] + 1e-8)
// grid = B_, block = COUT_
__global__ void k_demod() {
    __shared__ float s2[CIN_];
    const int b = blockIdx.x;
    const int co = threadIdx.x;
    float sv = g_s[b * CIN_ + threadIdx.x];
    s2[threadIdx.x] = sv * sv;
    __syncthreads();
    float acc = 0.f;
    const float* wq = g_wsq + co * CIN_;
    #pragma unroll 8
    for (int ci = 0; ci < CIN_; ci++)
        acc += s2[ci] * wq[ci];
    g_demod[b * COUT_ + co] = rsqrtf(acc * SCALE2 + 1e-8f);
}

// ---------------------------------------------------------------------------
// Kernel 4: the conv.
// Block = one (b, 8-cout tile, 16-row x 64-col spatial band).
// grid = (H/16, COUT/8, B), block = 256 threads.
// Thread t: hl = t>>4 (0..15), wq = t&15, owns output cols w0=4*wq..w0+3,
// for all 8 couts of the tile -> 32 accumulators.
#define TH 16
#define CO_TILE 8
#define SLAB_W 66              // 64 + 2 halo, even (keeps float2 alignment)
#define SLAB_ELEMS (18 * SLAB_W)

__global__ void __launch_bounds__(256, 2)
k_conv(const float* __restrict__ x,
       const float* __restrict__ weight,
       float* __restrict__ out) {
    __shared__ float xs[SLAB_ELEMS];     // 18 rows x 66 cols, 4.75 KB
    __shared__ float wsm[CO_TILE * 9];   // modulated weights for this cin

    const int tid = threadIdx.x;
    const int hl = tid >> 4;
    const int wq = tid & 15;
    const int w0 = wq << 2;

    const int h_base  = blockIdx.x * TH;
    const int co_base = blockIdx.y * CO_TILE;
    const int b       = blockIdx.z;

    const float* xb = x + (size_t)b * CIN_ * H_ * W_;
    const float* sb = g_s + b * CIN_;

    float acc[CO_TILE * 4];
    #pragma unroll
    for (int i = 0; i < CO_TILE * 4; i++) acc[i] = 0.f;

    for (int ci = 0; ci < CIN_; ci++) {
        __syncthreads();   // previous iteration's compute done before overwrite

        // stage x slab: rows h_base-1 .. h_base+16, cols -1..64 (zero-padded)
        const float* xp = xb + (size_t)ci * H_ * W_;
        for (int idx = tid; idx < SLAB_ELEMS; idx += 256) {
            int r = idx / SLAB_W;
            int c = idx - r * SLAB_W;
            int gh = h_base - 1 + r;
            int gw = c - 1;
            float v = 0.f;
            if (gh >= 0 && gh < H_ && gw >= 0 && gw < W_)
                v = xp[gh * W_ + gw];
            xs[idx] = v;
        }
        // stage modulated weights: w * s[ci]
        if (tid < CO_TILE * 9) {
            int co = tid / 9, kk = tid - co * 9;
            wsm[tid] = weight[((size_t)(co_base + co) * CIN_ + ci) * 9 + kk] * sb[ci];
        }
        __syncthreads();

        // load the 3x6 input window for this thread's 4 outputs (float2 loads)
        float xv[18];
        #pragma unroll
        for (int dr = 0; dr < 3; dr++) {
            #pragma unroll
            for (int q = 0; q < 3; q++) {
                float2 v = *reinterpret_cast<const float2*>(
                    &xs[(hl + dr) * SLAB_W + w0 + 2 * q]);
                xv[dr * 6 + 2 * q]     = v.x;
                xv[dr * 6 + 2 * q + 1] = v.y;
            }
        }

        #pragma unroll
        for (int co = 0; co < CO_TILE; co++) {
            float wv[9];
            #pragma unroll
            for (int k = 0; k < 9; k++) wv[k] = wsm[co * 9 + k];
            #pragma unroll
            for (int p = 0; p < 4; p++) {
                float a = acc[co * 4 + p];
                #pragma unroll
                for (int dr = 0; dr < 3; dr++) {
                    #pragma unroll
                    for (int dc = 0; dc < 3; dc++)
                        a += xv[dr * 6 + p + dc] * wv[dr * 3 + dc];
                }
                acc[co * 4 + p] = a;
            }
        }
    }

    // epilogue: apply mod_scale * demod, float4 coalesced stores
    #pragma unroll
    for (int co = 0; co < CO_TILE; co++) {
        float f = MOD_SCALE * g_demod[b * COUT_ + co_base + co];
        float4 o;
        o.x = acc[co * 4 + 0] * f;
        o.y = acc[co * 4 + 1] * f;
        o.z = acc[co * 4 + 2] * f;
        o.w = acc[co * 4 + 3] * f;
        float* op = out + (((size_t)(b * COUT_ + co_base + co) * H_) + (h_base + hl)) * W_ + w0;
        *reinterpret_cast<float4*>(op) = o;
    }
}

// ---------------------------------------------------------------------------
extern "C" void kernel_launch(void* const* d_in, const int* in_sizes, int n_in,
                              void* d_out, int out_size) {
    const float* x       = (const float*)d_in[0];  // [16,256,64,64]
    const float* style   = (const float*)d_in[1];  // [16,512]
    const float* weight  = (const float*)d_in[2];  // [256,256,3,3]
    const float* style_w = (const float*)d_in[3];  // [512,256]
    const float* style_b = (const float*)d_in[4];  // [256]
    float* out = (float*)d_out;

    k_style_proj<<<B_, CIN_>>>(style, style_w, style_b);
    k_wsq<<<COUT_, CIN_>>>(weight);
    k_demod<<<B_, COUT_>>>();

    dim3 grid(H_ / TH, COUT_ / CO_TILE, B_);
    k_conv<<<grid, 256>>>(x, weight, out);
}

// round 2
// speedup vs baseline: 6.9714x; 6.9714x over previous
#include <cuda_runtime.h>
#include <cuda_bf16.h>
#include <cstdint>

#define B_    16
#define CIN_  256
#define COUT_ 256
#define H_    64
#define W_    64
#define SDIM_ 512

#define MOD_SCALE (1.0f / 48.0f)
#define SCALE2    (1.0f / 2304.0f)

// scratch (__device__ globals are the allowed scratch mechanism)
__device__ float g_s[B_ * CIN_];                       // style projection
__device__ float g_demod[B_ * COUT_];                  // demod factors
__device__ float g_wsq[COUT_ * CIN_];                  // sum_k w^2
__device__ float g_wt[(size_t)B_ * 9 * CIN_ * COUT_];  // tf32 wmod, [b][tap][ci][co], 37.7MB

__device__ __forceinline__ float to_tf32(float f) {
    uint32_t u;
    asm("cvt.rna.tf32.f32 %0, %1;" : "=r"(u) : "f"(f));
    return __uint_as_float(u);
}

// ---------------------------------------------------------------------------
// K1: s[b][ci] = style[b] @ style_w[:,ci] + style_b[ci]
__global__ void k_style_proj(const float* __restrict__ style,
                             const float* __restrict__ style_w,
                             const float* __restrict__ style_b) {
    __shared__ float st[SDIM_];
    const int b = blockIdx.x, ci = threadIdx.x;
    for (int k = threadIdx.x; k < SDIM_; k += blockDim.x)
        st[k] = style[b * SDIM_ + k];
    __syncthreads();
    float acc = style_b[ci];
    #pragma unroll 8
    for (int k = 0; k < SDIM_; k++)
        acc += st[k] * style_w[k * CIN_ + ci];
    g_s[b * CIN_ + ci] = acc;
}

// K2: wsq[co][ci] = sum_k w^2
__global__ void k_wsq(const float* __restrict__ weight) {
    const int idx = blockIdx.x * blockDim.x + threadIdx.x;
    const float* wp = weight + (size_t)idx * 9;
    float s = 0.f;
    #pragma unroll
    for (int k = 0; k < 9; k++) { float v = wp[k]; s += v * v; }
    g_wsq[idx] = s;
}

// K3: demod[b][co] = rsqrt(scale2 * sum_ci s^2 * wsq + 1e-8)
__global__ void k_demod() {
    __shared__ float s2[CIN_];
    const int b = blockIdx.x, co = threadIdx.x;
    float sv = g_s[b * CIN_ + threadIdx.x];
    s2[threadIdx.x] = sv * sv;
    __syncthreads();
    float acc = 0.f;
    const float* wq = g_wsq + co * CIN_;
    #pragma unroll 8
    for (int ci = 0; ci < CIN_; ci++)
        acc += s2[ci] * wq[ci];
    g_demod[b * COUT_ + co] = rsqrtf(acc * SCALE2 + 1e-8f);
}

// ---------------------------------------------------------------------------
// K4: build wT[b][tap][ci][co] = tf32(w[co][ci][tap] * s[b][ci] * mod_scale * demod[b][co])
// grid (8 ci-tiles, 8 co-tiles, 16 b), block 256. smem transpose, coalesced in+out.
__global__ void k_wmod(const float* __restrict__ weight) {
    __shared__ float ws[32][289];   // [co][ci*9+tap], stride 289 -> conflict-free column reads
    const int b = blockIdx.z, ci0 = blockIdx.x * 32, co0 = blockIdx.y * 32;
    const int tid = threadIdx.x;

    // load 32 co-rows x 288 floats (32 ci x 9 taps), float4-coalesced
    for (int i = tid; i < 2304; i += 256) {
        int row = i / 72, q = i - row * 72;
        const float4 v = *(const float4*)(weight + (size_t)(co0 + row) * 2304 + (size_t)ci0 * 9 + q * 4);
        ws[row][q * 4 + 0] = v.x;
        ws[row][q * 4 + 1] = v.y;
        ws[row][q * 4 + 2] = v.z;
        ws[row][q * 4 + 3] = v.w;
    }
    __syncthreads();

    const int co = tid & 31;   // constant per thread
    const float dm = MOD_SCALE * g_demod[b * COUT_ + co0 + co];
    for (int i = tid; i < 9216; i += 256) {
        int t2 = i >> 5;                 // ci*9+tap  (same for whole warp)
        int ci = t2 / 9, tap = t2 - ci * 9;
        float v = ws[co][t2] * g_s[b * CIN_ + ci0 + ci] * dm;
        g_wt[(((size_t)(b * 9 + tap) * CIN_) + ci0 + ci) * COUT_ + co0 + co] = to_tf32(v);
    }
}

// ---------------------------------------------------------------------------
// K5: implicit-GEMM conv with mma.sync.m16n8k8 tf32.
// Block: 128 co x (2 rows x 64 cols) pixels, per batch. 8 warps (4 M x 2 N).
// grid (32 h-pairs, 2 co-tiles, 16 b), block 256.
#define KC 8
#define XS_CI_STRIDE 264          // 4 rows * 66 cols
#define WT_CO_STRIDE 136          // 128 co + pad 8 -> conflict-free A frags

__global__ void __launch_bounds__(256, 2)
k_conv(const float* __restrict__ x, float* __restrict__ out) {
    __shared__ float xs[KC * XS_CI_STRIDE];        // 8448 B
    __shared__ float wsT[9 * KC * WT_CO_STRIDE];   // 39168 B  (total 47616 < 48K)

    const int tid = threadIdx.x;
    const int lane = tid & 31, wid = tid >> 5;
    const int warp_m = wid >> 1, warp_n = wid & 1;
    const int g = lane >> 2, tig = lane & 3;

    const int h0 = blockIdx.x * 2;
    const int co_base = blockIdx.y * 128;
    const int b = blockIdx.z;

    const float* xb  = x + (size_t)b * CIN_ * H_ * W_;
    const float* wtb = g_wt + (size_t)b * 9 * CIN_ * COUT_;

    float acc[2][8][4];
    #pragma unroll
    for (int mt = 0; mt < 2; mt++)
        #pragma unroll
        for (int nt = 0; nt < 8; nt++)
            #pragma unroll
            for (int q = 0; q < 4; q++) acc[mt][nt][q] = 0.f;

    for (int ci0 = 0; ci0 < CIN_; ci0 += KC) {
        __syncthreads();

        // stage x slab: [ci][4 rows x 66 cols], tf32-rounded, zero-padded halo
        for (int i = tid; i < KC * XS_CI_STRIDE; i += 256) {
            int ci = i / XS_CI_STRIDE;
            int rem = i - ci * XS_CI_STRIDE;
            int r = rem / 66;
            int c = rem - r * 66;
            int gh = h0 - 1 + r, gw = c - 1;
            float v = 0.f;
            if ((unsigned)gh < (unsigned)H_ && (unsigned)gw < (unsigned)W_)
                v = xb[(size_t)(ci0 + ci) * (H_ * W_) + gh * W_ + gw];
            xs[i] = to_tf32(v);
        }
        // stage weights: wsT[tap][ci][co(128)] from wT, float4 in/out
        #pragma unroll
        for (int j = 0; j < 9; j++) {
            int i = tid + j * 256;          // 0..2303
            int row = i >> 5;               // tap*8+ci
            int tap = row >> 3, ci = row & 7;
            const float4 v = *(const float4*)(
                wtb + ((size_t)tap * CIN_ + ci0 + ci) * COUT_ + co_base + (i & 31) * 4);
            *(float4*)(&wsT[row * WT_CO_STRIDE + (i & 31) * 4]) = v;
        }
        __syncthreads();

        #pragma unroll
        for (int tap = 0; tap < 9; tap++) {
            const int dh = tap / 3, dw = tap - dh * 3;
            const float* wr = &wsT[tap * KC * WT_CO_STRIDE];

            uint32_t a[2][4];
            #pragma unroll
            for (int mt = 0; mt < 2; mt++) {
                int m = warp_m * 32 + mt * 16;
                a[mt][0] = __float_as_uint(wr[tig * WT_CO_STRIDE + m + g]);
                a[mt][1] = __float_as_uint(wr[tig * WT_CO_STRIDE + m + g + 8]);
                a[mt][2] = __float_as_uint(wr[(tig + 4) * WT_CO_STRIDE + m + g]);
                a[mt][3] = __float_as_uint(wr[(tig + 4) * WT_CO_STRIDE + m + g + 8]);
            }
            const int rowoff = (warp_n + dh) * 66 + dw;
            #pragma unroll
            for (int nt = 0; nt < 8; nt++) {
                int cb = nt * 8 + g;
                uint32_t b0 = __float_as_uint(xs[tig * XS_CI_STRIDE + rowoff + cb]);
                uint32_t b1 = __float_as_uint(xs[(tig + 4) * XS_CI_STRIDE + rowoff + cb]);
                #pragma unroll
                for (int mt = 0; mt < 2; mt++) {
                    asm volatile(
                        "mma.sync.aligned.m16n8k8.row.col.f32.tf32.tf32.f32 "
                        "{%0,%1,%2,%3}, {%4,%5,%6,%7}, {%8,%9}, {%0,%1,%2,%3};\n"
                        : "+f"(acc[mt][nt][0]), "+f"(acc[mt][nt][1]),
                          "+f"(acc[mt][nt][2]), "+f"(acc[mt][nt][3])
                        : "r"(a[mt][0]), "r"(a[mt][1]), "r"(a[mt][2]), "r"(a[mt][3]),
                          "r"(b0), "r"(b1));
                }
            }
        }
    }

    // epilogue: scaling already folded into weights; raw store, float2 pairs
    const int h = h0 + warp_n;
    #pragma unroll
    for (int mt = 0; mt < 2; mt++) {
        int co_lo = co_base + warp_m * 32 + mt * 16 + g;
        #pragma unroll
        for (int nt = 0; nt < 8; nt++) {
            int w = nt * 8 + tig * 2;
            float* p0 = out + (((size_t)(b * COUT_ + co_lo)) * H_ + h) * W_ + w;
            *(float2*)p0 = make_float2(acc[mt][nt][0], acc[mt][nt][1]);
            float* p1 = p0 + (size_t)8 * H_ * W_;      // co + 8
            *(float2*)p1 = make_float2(acc[mt][nt][2], acc[mt][nt][3]);
        }
    }
}

// ---------------------------------------------------------------------------
extern "C" void kernel_launch(void* const* d_in, const int* in_sizes, int n_in,
                              void* d_out, int out_size) {
    const float* x       = (const float*)d_in[0];  // [16,256,64,64]
    const float* style   = (const float*)d_in[1];  // [16,512]
    const float* weight  = (const float*)d_in[2];  // [256,256,3,3]
    const float* style_w = (const float*)d_in[3];  // [512,256]
    const float* style_b = (const float*)d_in[4];  // [256]
    float* out = (float*)d_out;

    k_style_proj<<<B_, CIN_>>>(style, style_w, style_b);
    k_wsq<<<COUT_, CIN_>>>(weight);
    k_demod<<<B_, COUT_>>>();

    dim3 gw(8, 8, B_);
    k_wmod<<<gw, 256>>>(weight);

    dim3 gc(H_ / 2, COUT_ / 128, B_);
    k_conv<<<gc, 256>>>(x, out);
}

// round 4
// speedup vs baseline: 10.3247x; 1.4810x over previous
#include <cuda_runtime.h>
#include <cuda_fp16.h>
#include <cstdint>

#define B_    16
#define CIN_  256
#define COUT_ 256
#define H_    64
#define W_    64
#define SDIM_ 512

#define MOD_SCALE (1.0f / 48.0f)
#define SCALE2    (1.0f / 2304.0f)

// scratch
__device__ float g_s[B_ * CIN_];
__device__ float g_demod[B_ * COUT_];
__device__ float g_wsq[COUT_ * CIN_];
// fp16 modulated weights, layout [b][tap][co][ci]  (ci fastest) — 18.9 MB
__device__ __half g_wth[(size_t)B_ * 9 * COUT_ * CIN_];

// ---------------------------------------------------------------------------
// K1: style projection
__global__ void k_style_proj(const float* __restrict__ style,
                             const float* __restrict__ style_w,
                             const float* __restrict__ style_b) {
    __shared__ float st[SDIM_];
    const int b = blockIdx.x, ci = threadIdx.x;
    for (int k = threadIdx.x; k < SDIM_; k += blockDim.x)
        st[k] = style[b * SDIM_ + k];
    __syncthreads();
    float acc = style_b[ci];
    #pragma unroll 8
    for (int k = 0; k < SDIM_; k++)
        acc += st[k] * style_w[k * CIN_ + ci];
    g_s[b * CIN_ + ci] = acc;
}

// K2: wsq[co][ci] = sum_k w^2
__global__ void k_wsq(const float* __restrict__ weight) {
    const int idx = blockIdx.x * blockDim.x + threadIdx.x;
    const float* wp = weight + (size_t)idx * 9;
    float s = 0.f;
    #pragma unroll
    for (int k = 0; k < 9; k++) { float v = wp[k]; s += v * v; }
    g_wsq[idx] = s;
}

// K3: demod
__global__ void k_demod() {
    __shared__ float s2[CIN_];
    const int b = blockIdx.x, co = threadIdx.x;
    float sv = g_s[b * CIN_ + threadIdx.x];
    s2[threadIdx.x] = sv * sv;
    __syncthreads();
    float acc = 0.f;
    const float* wq = g_wsq + co * CIN_;
    #pragma unroll 8
    for (int ci = 0; ci < CIN_; ci++)
        acc += s2[ci] * wq[ci];
    g_demod[b * COUT_ + co] = rsqrtf(acc * SCALE2 + 1e-8f);
}

// ---------------------------------------------------------------------------
// K4: g_wth[b][tap][co][ci] = fp16(w[co][ci][tap] * s[b][ci] * MOD_SCALE * demod[b][co])
// grid (8 ci-tiles, 8 co-tiles, 16 b), block 256.
__global__ void k_wmod_h(const float* __restrict__ weight) {
    __shared__ float ws[32][289];    // [co][ci*9+tap]; 9ci%32 distinct -> conflict-free
    __shared__ float ssm[32], dsm[32];
    const int b = blockIdx.z, ci0 = blockIdx.x * 32, co0 = blockIdx.y * 32;
    const int tid = threadIdx.x;

    for (int i = tid; i < 2304; i += 256) {
        int row = i / 72, q = i - row * 72;
        const float4 v = *(const float4*)(weight + (size_t)(co0 + row) * 2304 + (size_t)ci0 * 9 + q * 4);
        ws[row][q * 4 + 0] = v.x;
        ws[row][q * 4 + 1] = v.y;
        ws[row][q * 4 + 2] = v.z;
        ws[row][q * 4 + 3] = v.w;
    }
    if (tid < 32) {
        ssm[tid] = g_s[b * CIN_ + ci0 + tid];
        dsm[tid] = MOD_SCALE * g_demod[b * COUT_ + co0 + tid];
    }
    __syncthreads();

    for (int i = tid; i < 9216; i += 256) {
        int ci = i & 31, co = (i >> 5) & 31, tap = i >> 10;
        float v = ws[co][ci * 9 + tap] * ssm[ci] * dsm[co];
        g_wth[((size_t)(b * 9 + tap) * COUT_ + co0 + co) * CIN_ + ci0 + ci] = __float2half_rn(v);
    }
}

// ---------------------------------------------------------------------------
// K5: implicit-GEMM conv with mma.sync.m16n8k16 fp16 (fp32 accum).
// Block: 128 co x (2 rows x 64 cols). 8 warps = 4M x 2N. KC=16 ci per chunk.
// grid (32 h-pairs, 2 co-tiles, 16 b), block 256.
#define KC 16

__global__ void __launch_bounds__(256, 2)
k_conv(const float* __restrict__ x, float* __restrict__ out) {
    __shared__ __half xs[264 * KC];          // [px(4r x 66c)][ci]   8448 B
    __shared__ __half wsT[9 * 128 * KC];     // [tap][co][ci]       36864 B

    const int tid = threadIdx.x;
    const int lane = tid & 31, wid = tid >> 5;
    const int warp_m = wid >> 1, warp_n = wid & 1;
    const int g = lane >> 2, tig = lane & 3;

    const int h0 = blockIdx.x * 2;
    const int co_base = blockIdx.y * 128;
    const int b = blockIdx.z;

    const float* xb = x + (size_t)b * CIN_ * (H_ * W_);
    const __half* wtb = g_wth + (size_t)b * 9 * COUT_ * CIN_;

    float acc[2][8][4];
    #pragma unroll
    for (int mt = 0; mt < 2; mt++)
        #pragma unroll
        for (int nt = 0; nt < 8; nt++)
            #pragma unroll
            for (int q = 0; q < 4; q++) acc[mt][nt][q] = 0.f;

    for (int ci0 = 0; ci0 < CIN_; ci0 += KC) {
        __syncthreads();   // previous chunk's compute done before overwrite

        // --- A: cp.async  wsT[tap][co][0..15] <- g_wth (16B x 2 per row) ---
        {
            const uint32_t wbase = (uint32_t)__cvta_generic_to_shared(wsT);
            #pragma unroll
            for (int j = 0; j < 9; j++) {
                int u = tid + j * 256;          // 0..2303
                int row = u >> 1, hl = u & 1;   // row = tap*128+co
                int tap = row >> 7, co = row & 127;
                const __half* src = wtb + ((size_t)tap * COUT_ + co_base + co) * CIN_ + ci0 + hl * 8;
                uint32_t dst = wbase + row * 32 + hl * 16;
                asm volatile("cp.async.ca.shared.global [%0], [%1], 16;"
                             :: "r"(dst), "l"(src));
            }
            asm volatile("cp.async.commit_group;");
        }

        // --- B: stage x[ci0..ci0+15] for 264 px (4 rows x 66 cols, halo 0-pad) ---
        for (int px = tid; px < 264; px += 256) {
            int r = px / 66, c = px - r * 66;
            int gh = h0 - 1 + r, gw = c - 1;
            __half2* dst = (__half2*)&xs[px * KC];
            if ((unsigned)gh < (unsigned)H_ && (unsigned)gw < (unsigned)W_) {
                const float* xp = xb + gh * W_ + gw + (size_t)ci0 * (H_ * W_);
                #pragma unroll
                for (int c2 = 0; c2 < KC / 2; c2++) {
                    float v0 = xp[(size_t)(2 * c2) * (H_ * W_)];
                    float v1 = xp[(size_t)(2 * c2 + 1) * (H_ * W_)];
                    dst[c2] = __floats2half2_rn(v0, v1);
                }
            } else {
                #pragma unroll
                for (int c2 = 0; c2 < KC / 2; c2++)
                    dst[c2] = __floats2half2_rn(0.f, 0.f);
            }
        }

        asm volatile("cp.async.wait_group 0;" ::: "memory");
        __syncthreads();

        // --- compute: 9 taps x 2 mt x 8 nt mma.m16n8k16 ---
        #pragma unroll
        for (int tap = 0; tap < 9; tap++) {
            const int dh = tap / 3, dw = tap - dh * 3;
            const __half* wr = &wsT[tap * 128 * KC];

            uint32_t a[2][4];
            #pragma unroll
            for (int mt = 0; mt < 2; mt++) {
                int m = warp_m * 32 + mt * 16;
                a[mt][0] = *(const uint32_t*)&wr[(m + g) * KC + tig * 2];
                a[mt][1] = *(const uint32_t*)&wr[(m + g + 8) * KC + tig * 2];
                a[mt][2] = *(const uint32_t*)&wr[(m + g) * KC + tig * 2 + 8];
                a[mt][3] = *(const uint32_t*)&wr[(m + g + 8) * KC + tig * 2 + 8];
            }
            const int rowoff = (warp_n + dh) * 66 + dw;
            #pragma unroll
            for (int nt = 0; nt < 8; nt++) {
                int cb = nt * 8 + g;
                uint32_t b0 = *(const uint32_t*)&xs[(rowoff + cb) * KC + tig * 2];
                uint32_t b1 = *(const uint32_t*)&xs[(rowoff + cb) * KC + tig * 2 + 8];
                #pragma unroll
                for (int mt = 0; mt < 2; mt++) {
                    asm volatile(
                        "mma.sync.aligned.m16n8k16.row.col.f32.f16.f16.f32 "
                        "{%0,%1,%2,%3}, {%4,%5,%6,%7}, {%8,%9}, {%0,%1,%2,%3};\n"
                        : "+f"(acc[mt][nt][0]), "+f"(acc[mt][nt][1]),
                          "+f"(acc[mt][nt][2]), "+f"(acc[mt][nt][3])
                        : "r"(a[mt][0]), "r"(a[mt][1]), "r"(a[mt][2]), "r"(a[mt][3]),
                          "r"(b0), "r"(b1));
                }
            }
        }
    }

    // epilogue: scaling folded into weights; float2 stores
    const int h = h0 + warp_n;
    #pragma unroll
    for (int mt = 0; mt < 2; mt++) {
        int co_lo = co_base + warp_m * 32 + mt * 16 + g;
        #pragma unroll
        for (int nt = 0; nt < 8; nt++) {
            int w = nt * 8 + tig * 2;
            float* p0 = out + (((size_t)(b * COUT_ + co_lo)) * H_ + h) * W_ + w;
            *(float2*)p0 = make_float2(acc[mt][nt][0], acc[mt][nt][1]);
            float* p1 = p0 + (size_t)8 * H_ * W_;
            *(float2*)p1 = make_float2(acc[mt][nt][2], acc[mt][nt][3]);
        }
    }
}

// ---------------------------------------------------------------------------
extern "C" void kernel_launch(void* const* d_in, const int* in_sizes, int n_in,
                              void* d_out, int out_size) {
    const float* x       = (const float*)d_in[0];
    const float* style   = (const float*)d_in[1];
    const float* weight  = (const float*)d_in[2];
    const float* style_w = (const float*)d_in[3];
    const float* style_b = (const float*)d_in[4];
    float* out = (float*)d_out;

    k_style_proj<<<B_, CIN_>>>(style, style_w, style_b);
    k_wsq<<<COUT_, CIN_>>>(weight);
    k_demod<<<B_, COUT_>>>();

    dim3 gw(8, 8, B_);
    k_wmod_h<<<gw, 256>>>(weight);

    dim3 gc(H_ / 2, COUT_ / 128, B_);
    k_conv<<<gc, 256>>>(x, out);
}